// round 6
// baseline (speedup 1.0000x reference)
#include <cuda_runtime.h>
#include <cuda_fp16.h>

#define BB 2048
#define SS 1024
#define FF 64
#define NQ 16            // feature quads (4 features each)
#define BI 32
#define BJ 64
#define TI 4
#define TJ 4

// Quad-product tables, quad-major. For quad q (features 4q..4q+3), row r:
// record = 4 half2: lane0 from pair (4q,4q+1), lane1 from pair (4q+2,4q+3):
//   h[0]={c0c1,c2c3} h[1]={c0s1,c2s3} h[2]={s0c1,s2c3} h[3]={s0s1,s2s3}
// where c_k=cos(v[4q+k]/2), s_k=sin(v[4q+k]/2).
__device__ uint4 g_A4[NQ * BB];   // X side
__device__ uint4 g_B4[NQ * SS];   // support side

union U16 { uint4 u; __half2 h[4]; };

// Coalesced load -> fp32 sincos -> smem transpose -> quad-product uint4 records.
// 32 rows per block; blocks 0..7 also init out[i] = b.
__global__ __launch_bounds__(256) void precomp_kernel(const float* __restrict__ X,
                                                      const float* __restrict__ Sp,
                                                      const float* __restrict__ b,
                                                      float* __restrict__ out) {
    __shared__ float sc[FF][33];
    __shared__ float ss[FF][33];
    const int blk = blockIdx.x;       // 0..95: [0,64) -> X, [64,96) -> S
    const int tid = threadIdx.x;

    const float* src;
    uint4* dst;
    int N, i0;
    if (blk < 64) { src = X;  dst = g_A4; N = BB; i0 = blk * 32; }
    else          { src = Sp; dst = g_B4; N = SS; i0 = (blk - 64) * 32; }

    // Read 32 rows x 64 f (8 passes, lanes step f -> coalesced).
#pragma unroll
    for (int p = 0; p < 8; p++) {
        int l = p * 256 + tid;
        int r = l >> 6;          // 0..31
        int f = l & 63;
        float v = src[(i0 + r) * FF + f];
        float s, c;
        __sincosf(0.5f * v, &s, &c);
        sc[f][r] = c;            // stride-33: conflict-free
        ss[f][r] = s;
    }
    __syncthreads();
    // Build quad records: 16 q x 32 rows = 512 items, 2 passes.
#pragma unroll
    for (int p = 0; p < 2; p++) {
        int l = p * 256 + tid;
        int q = l >> 5;          // 0..15
        int i = l & 31;
        float c0 = sc[4 * q + 0][i], s0 = ss[4 * q + 0][i];
        float c1 = sc[4 * q + 1][i], s1 = ss[4 * q + 1][i];
        float c2 = sc[4 * q + 2][i], s2 = ss[4 * q + 2][i];
        float c3 = sc[4 * q + 3][i], s3 = ss[4 * q + 3][i];
        U16 rec;
        rec.h[0] = __floats2half2_rn(c0 * c1, c2 * c3);
        rec.h[1] = __floats2half2_rn(c0 * s1, c2 * s3);
        rec.h[2] = __floats2half2_rn(s0 * c1, s2 * c3);
        rec.h[3] = __floats2half2_rn(s0 * s1, s2 * s3);
        dst[q * N + i0 + i] = rec.u;
    }
    if (blk < 8) out[blk * 256 + tid] = b[0];
}

__global__ __launch_bounds__(128, 8) void main_kernel(const float* __restrict__ W,
                                                      float* __restrict__ out) {
    __shared__ __align__(16) uint4 sA[NQ][BI];   // 8 KB
    __shared__ __align__(16) uint4 sB[NQ][BJ];   // 16 KB
    __shared__ float sW[BJ];

    const int tid = threadIdx.x;
    const int tx = tid & 15;   // j: handles {tx, tx+16, tx+32, tx+48}
    const int ty = tid >> 4;   // i: handles ty*4 .. ty*4+3
    const int i0 = blockIdx.x * BI;
    const int j0 = blockIdx.y * BJ;

    if (tid < BJ) sW[tid] = W[j0 + tid];

    // Fill: A = 512 uint4 (4 passes), B = 1024 uint4 (8 passes). Coalesced.
#pragma unroll
    for (int p = 0; p < 4; p++) {
        int l = p * 128 + tid;
        sA[l >> 5][l & 31] = g_A4[(l >> 5) * BB + i0 + (l & 31)];
    }
#pragma unroll
    for (int p = 0; p < 8; p++) {
        int l = p * 128 + tid;
        sB[l >> 6][l & 63] = g_B4[(l >> 6) * SS + j0 + (l & 63)];
    }
    __syncthreads();

    // acc[a][b] lanes: {prod of t-pairs (even pair), (odd pair)} per quad.
    __half2 acc[TI][TJ];
    const __half2 one2 = __floats2half2_rn(1.0f, 1.0f);
#pragma unroll
    for (int a = 0; a < TI; a++)
#pragma unroll
        for (int b = 0; b < TJ; b++) acc[a][b] = one2;

#pragma unroll 2
    for (int q = 0; q < NQ; q++) {
        U16 av[TI], bv[TJ];
#pragma unroll
        for (int a = 0; a < TI; a++) av[a].u = sA[q][ty * TI + a];   // broadcast
#pragma unroll
        for (int b = 0; b < TJ; b++) bv[b].u = sB[q][tx + 16 * b];   // contiguous
#pragma unroll
        for (int a = 0; a < TI; a++) {
#pragma unroll
            for (int b = 0; b < TJ; b++) {
                // h = {t(f0)t(f1), t(f2)t(f3)} via 4-term dot of quad products
                __half2 h = __hmul2(av[a].h[0], bv[b].h[0]);
                h = __hfma2(av[a].h[1], bv[b].h[1], h);
                h = __hfma2(av[a].h[2], bv[b].h[2], h);
                h = __hfma2(av[a].h[3], bv[b].h[3], h);
                acc[a][b] = __hmul2(acc[a][b], h);
            }
        }
    }

    // K = (lane0 * lane1)^2 in fp32; weight; reduce over 16 tx threads.
#pragma unroll
    for (int a = 0; a < TI; a++) {
        float p = 0.0f;
#pragma unroll
        for (int b = 0; b < TJ; b++) {
            float2 pe = __half22float2(acc[a][b]);
            float pt = pe.x * pe.y;
            p = fmaf(pt * pt, sW[tx + 16 * b], p);
        }
#pragma unroll
        for (int off = 8; off > 0; off >>= 1)
            p += __shfl_down_sync(0xffffffffu, p, off, 16);
        if (tx == 0) atomicAdd(&out[i0 + ty * TI + a], p);
    }
}

extern "C" void kernel_launch(void* const* d_in, const int* in_sizes, int n_in,
                              void* d_out, int out_size) {
    const float* X  = (const float*)d_in[0];  // [2048, 64]
    const float* Sp = (const float*)d_in[1];  // [1024, 64]
    const float* W  = (const float*)d_in[2];  // [1, 1024]
    const float* b  = (const float*)d_in[3];  // [1]
    float* out = (float*)d_out;               // [2048]

    precomp_kernel<<<96, 256>>>(X, Sp, b, out);   // quad tables + out=b init

    dim3 grid(BB / BI, SS / BJ);  // 64 x 16 = 1024 CTAs, 128 thr, occ 8
    main_kernel<<<grid, 128>>>(W, out);
}

// round 11
// speedup vs baseline: 1.4168x; 1.4168x over previous
#include <cuda_runtime.h>
#include <cuda_bf16.h>
#include <cstdint>

#define BB 2048
#define SS 1024
#define FF 64
// 16 groups of 4 features; per group a 16-entry bf16 table per row.
// Group panel per 64-row block: 64 rows x 32 B (swizzled), 2 KB.
// Global layout: [blk][g][2KB]  -> 32 KB per 64-row block.

__device__ __align__(16) unsigned char g_A[(BB / 64) * 32768];   // 1 MB
__device__ __align__(16) unsigned char g_B[(SS / 64) * 32768];   // 512 KB

__device__ __forceinline__ uint32_t swz(uint32_t o) {            // 16B-chunk XOR swizzle
    return o ^ (((o >> 7) & 1u) << 4);
}
__device__ __forceinline__ uint32_t smem_u32(const void* p) {
    uint32_t a;
    asm("{ .reg .u64 t; cvta.to.shared.u64 t, %1; cvt.u32.u64 %0, t; }" : "=r"(a) : "l"(p));
    return a;
}
#define LDSM4(r0, r1, r2, r3, addr) \
    asm volatile("ldmatrix.sync.aligned.m8n8.x4.shared.b16 {%0,%1,%2,%3}, [%4];" \
                 : "=r"(r0), "=r"(r1), "=r"(r2), "=r"(r3) : "r"(addr))

__device__ __forceinline__ void mma_bf16(float d[4], uint32_t a0, uint32_t a1, uint32_t a2,
                                         uint32_t a3, uint32_t b0, uint32_t b1) {
    asm("mma.sync.aligned.m16n8k16.row.col.f32.bf16.bf16.f32 "
        "{%0,%1,%2,%3}, {%4,%5,%6,%7}, {%8,%9}, {%10,%11,%12,%13};"
        : "=f"(d[0]), "=f"(d[1]), "=f"(d[2]), "=f"(d[3])
        : "r"(a0), "r"(a1), "r"(a2), "r"(a3), "r"(b0), "r"(b1),
          "f"(0.0f), "f"(0.0f), "f"(0.0f), "f"(0.0f));
}

// ---- precompute: per-row 16-entry group tables, pre-swizzled ----
__global__ __launch_bounds__(256) void precomp_kernel(const float* __restrict__ X,
                                                      const float* __restrict__ Sp,
                                                      const float* __restrict__ b,
                                                      float* __restrict__ out) {
    __shared__ float sc[FF][33];
    __shared__ float ss[FF][33];
    const int blk = blockIdx.x;       // [0,64): X rows, [64,96): support rows
    const int tid = threadIdx.x;
    const bool isA = blk < 64;
    const float* src = isA ? X : Sp;
    unsigned char* dst = isA ? g_A : g_B;
    const int i0 = isA ? blk * 32 : (blk - 64) * 32;

    // 32 rows x 64 features, coalesced loads, fast sincos
#pragma unroll
    for (int p = 0; p < 8; p++) {
        int l = p * 256 + tid;
        int r = l >> 6, f = l & 63;
        float s, c;
        __sincosf(0.5f * src[(i0 + r) * FF + f], &s, &c);
        sc[f][r] = c;
        ss[f][r] = s;
    }
    __syncthreads();

    // 32 rows x 16 groups = 512 tasks: build 16 sign-pattern products each
#pragma unroll
    for (int p = 0; p < 2; p++) {
        int task = p * 256 + tid;
        int r = task >> 4, g = task & 15;
        float c0 = sc[4*g+0][r], s0 = ss[4*g+0][r];
        float c1 = sc[4*g+1][r], s1 = ss[4*g+1][r];
        float c2 = sc[4*g+2][r], s2 = ss[4*g+2][r];
        float c3 = sc[4*g+3][r], s3 = ss[4*g+3][r];
        float q01[4] = {c0*c1, s0*c1, c0*s1, s0*s1};   // bit0 -> f0, bit1 -> f1
        float q23[4] = {c2*c3, s2*c3, c2*s3, s2*s3};   // bit0 -> f2, bit1 -> f3
        uint32_t w[8];
#pragma unroll
        for (int mp = 0; mp < 8; mp++) {
            float e0 = q01[(2*mp)     & 3] * q23[(2*mp)     >> 2];
            float e1 = q01[(2*mp + 1) & 3] * q23[(2*mp + 1) >> 2];
            w[mp] = (uint32_t)__bfloat16_as_ushort(__float2bfloat16(e0))
                  | ((uint32_t)__bfloat16_as_ushort(__float2bfloat16(e1)) << 16);
        }
        int R = i0 + r;
        unsigned char* base = dst + ((R >> 6) * 16 + g) * 2048;
        *(uint4*)(base + swz((R & 63) * 32))      = make_uint4(w[0], w[1], w[2], w[3]);
        *(uint4*)(base + swz((R & 63) * 32 + 16)) = make_uint4(w[4], w[5], w[6], w[7]);
    }
    if (blk < 8) out[blk * 256 + tid] = b[0];
}

// ---- main: 16 K=16 bf16 MMAs per tile; multiply the 16 G-planes ----
__global__ __launch_bounds__(128) void main_kernel(const float* __restrict__ W,
                                                   float* __restrict__ out) {
    __shared__ __align__(16) unsigned char sA[8 * 2048];   // 16 KB (8 groups)
    __shared__ __align__(16) unsigned char sB[8 * 2048];   // 16 KB
    __shared__ float sW[64];

    const int tid = threadIdx.x;
    const int lane = tid & 31;
    const int w = tid >> 5;                 // warp: rows w*16 .. w*16+15
    const uint32_t aBase = smem_u32(sA);
    const uint32_t bBase = smem_u32(sB);

    // ldmatrix per-lane row offsets (fixed across groups)
    // A tiles: (rows0-7,k0-7)(rows8-15,k0-7)(rows0-7,k8-15)(rows8-15,k8-15)
    const uint32_t aoff = swz(((w << 4) + (lane & 15)) * 32 + (lane >> 4) * 16);
    // B tiles: (j0-7,k0-7)(j0-7,k8-15)(j8-15,k0-7)(j8-15,k8-15)
    const int jr = (lane & 7) + ((lane >> 4) << 3);
    const uint32_t bkc = (lane >> 3) & 1;

    float P[32];
#pragma unroll
    for (int t = 0; t < 32; t++) P[t] = 1.0f;

    if (tid < 64) sW[tid] = W[blockIdx.y * 64 + tid];

    for (int pass = 0; pass < 2; pass++) {
        __syncthreads();
        const uint4* gA = (const uint4*)(g_A + blockIdx.x * 32768 + pass * 16384);
        const uint4* gB = (const uint4*)(g_B + blockIdx.y * 32768 + pass * 16384);
#pragma unroll
        for (int k = 0; k < 8; k++) {
            ((uint4*)sA)[k * 128 + tid] = gA[k * 128 + tid];
            ((uint4*)sB)[k * 128 + tid] = gB[k * 128 + tid];
        }
        __syncthreads();

#pragma unroll
        for (int g = 0; g < 8; g++) {
            uint32_t a0, a1, a2, a3;
            LDSM4(a0, a1, a2, a3, aBase + g * 2048 + aoff);
#pragma unroll
            for (int nb = 0; nb < 4; nb++) {
                uint32_t b0, b1, b2, b3;
                LDSM4(b0, b1, b2, b3,
                      bBase + g * 2048 + swz((nb * 16 + jr) * 32 + bkc * 16));
                float d[4];
                mma_bf16(d, a0, a1, a2, a3, b0, b1);      // j = nb*16 + 0..7
                P[nb*8 + 0] *= d[0]; P[nb*8 + 1] *= d[1];
                P[nb*8 + 2] *= d[2]; P[nb*8 + 3] *= d[3];
                mma_bf16(d, a0, a1, a2, a3, b2, b3);      // j = nb*16 + 8..15
                P[nb*8 + 4] *= d[0]; P[nb*8 + 5] *= d[1];
                P[nb*8 + 6] *= d[2]; P[nb*8 + 7] *= d[3];
            }
        }
    }

    // K = P^2; weight; reduce over the quad (lanes sharing lane>>2).
    float r0 = 0.0f, r1 = 0.0f;
#pragma unroll
    for (int t = 0; t < 8; t++) {
        int j = t * 8 + (lane & 3) * 2;
        float w0 = sW[j], w1 = sW[j + 1];
        r0 = fmaf(P[t*4 + 0] * P[t*4 + 0], w0, r0);
        r0 = fmaf(P[t*4 + 1] * P[t*4 + 1], w1, r0);
        r1 = fmaf(P[t*4 + 2] * P[t*4 + 2], w0, r1);
        r1 = fmaf(P[t*4 + 3] * P[t*4 + 3], w1, r1);
    }
    r0 += __shfl_xor_sync(0xffffffffu, r0, 1);
    r0 += __shfl_xor_sync(0xffffffffu, r0, 2);
    r1 += __shfl_xor_sync(0xffffffffu, r1, 1);
    r1 += __shfl_xor_sync(0xffffffffu, r1, 2);
    if ((lane & 3) == 0) {
        int row = blockIdx.x * 64 + w * 16 + (lane >> 2);
        atomicAdd(&out[row], r0);
        atomicAdd(&out[row + 8], r1);
    }
}

extern "C" void kernel_launch(void* const* d_in, const int* in_sizes, int n_in,
                              void* d_out, int out_size) {
    const float* X  = (const float*)d_in[0];  // [2048, 64]
    const float* Sp = (const float*)d_in[1];  // [1024, 64]
    const float* W  = (const float*)d_in[2];  // [1, 1024]
    const float* b  = (const float*)d_in[3];  // [1]
    float* out = (float*)d_out;               // [2048]

    precomp_kernel<<<96, 256>>>(X, Sp, b, out);   // tables + out=b init

    dim3 grid(BB / 64, SS / 64);                  // 32 x 16 = 512 CTAs
    main_kernel<<<grid, 128>>>(W, out);
}

// round 13
// speedup vs baseline: 1.4449x; 1.0198x over previous
#include <cuda_runtime.h>
#include <cuda_bf16.h>
#include <cstdint>

#define BB 2048
#define SS 1024
#define FF 64
// 16 groups of 4 features; per group a 16-entry bf16 table per row.
// Per 64-row block per group: 64 rows x 32 B (swizzled) = 2 KB panel.
// Global layout: [blk][g][2KB] -> 32 KB per 64-row block.

__device__ __align__(16) unsigned char g_A[(BB / 64) * 32768];   // 1 MB
__device__ __align__(16) unsigned char g_B[(SS / 64) * 32768];   // 512 KB

__device__ __forceinline__ uint32_t swz(uint32_t o) {            // 16B-chunk XOR swizzle
    return o ^ (((o >> 7) & 1u) << 4);
}
__device__ __forceinline__ uint32_t smem_u32(const void* p) {
    uint32_t a;
    asm("{ .reg .u64 t; cvta.to.shared.u64 t, %1; cvt.u32.u64 %0, t; }" : "=r"(a) : "l"(p));
    return a;
}
#define LDSM4(r0, r1, r2, r3, addr) \
    asm volatile("ldmatrix.sync.aligned.m8n8.x4.shared.b16 {%0,%1,%2,%3}, [%4];" \
                 : "=r"(r0), "=r"(r1), "=r"(r2), "=r"(r3) : "r"(addr))

__device__ __forceinline__ void mma_bf16(float d[4], uint32_t a0, uint32_t a1, uint32_t a2,
                                         uint32_t a3, uint32_t b0, uint32_t b1) {
    asm("mma.sync.aligned.m16n8k16.row.col.f32.bf16.bf16.f32 "
        "{%0,%1,%2,%3}, {%4,%5,%6,%7}, {%8,%9}, {%10,%11,%12,%13};"
        : "=f"(d[0]), "=f"(d[1]), "=f"(d[2]), "=f"(d[3])
        : "r"(a0), "r"(a1), "r"(a2), "r"(a3), "r"(b0), "r"(b1),
          "f"(0.0f), "f"(0.0f), "f"(0.0f), "f"(0.0f));
}

// ---- precompute: per-row 16-entry group tables, pre-swizzled. 16 rows/block. ----
__global__ __launch_bounds__(256) void precomp_kernel(const float* __restrict__ X,
                                                      const float* __restrict__ Sp,
                                                      const float* __restrict__ b,
                                                      float* __restrict__ out) {
    __shared__ float sc[FF][17];
    __shared__ float ss[FF][17];
    const int blk = blockIdx.x;       // [0,128): X rows, [128,192): support rows
    const int tid = threadIdx.x;
    const bool isA = blk < 128;
    const float* src = isA ? X : Sp;
    unsigned char* dst = isA ? g_A : g_B;
    const int i0 = isA ? blk * 16 : (blk - 128) * 16;

    // 16 rows x 64 features, coalesced loads, fast sincos
#pragma unroll
    for (int p = 0; p < 4; p++) {
        int l = p * 256 + tid;
        int r = l >> 6, f = l & 63;
        float s, c;
        __sincosf(0.5f * src[(i0 + r) * FF + f], &s, &c);
        sc[f][r] = c;
        ss[f][r] = s;
    }
    __syncthreads();

    // 16 rows x 16 groups = 256 tasks: build 16 sign-pattern products each
    {
        int r = tid >> 4, g = tid & 15;
        float c0 = sc[4*g+0][r], s0 = ss[4*g+0][r];
        float c1 = sc[4*g+1][r], s1 = ss[4*g+1][r];
        float c2 = sc[4*g+2][r], s2 = ss[4*g+2][r];
        float c3 = sc[4*g+3][r], s3 = ss[4*g+3][r];
        float q01[4] = {c0*c1, s0*c1, c0*s1, s0*s1};   // bit0 -> f0, bit1 -> f1
        float q23[4] = {c2*c3, s2*c3, c2*s3, s2*s3};   // bit0 -> f2, bit1 -> f3
        uint32_t w[8];
#pragma unroll
        for (int mp = 0; mp < 8; mp++) {
            float e0 = q01[(2*mp)     & 3] * q23[(2*mp)     >> 2];
            float e1 = q01[(2*mp + 1) & 3] * q23[(2*mp + 1) >> 2];
            w[mp] = (uint32_t)__bfloat16_as_ushort(__float2bfloat16(e0))
                  | ((uint32_t)__bfloat16_as_ushort(__float2bfloat16(e1)) << 16);
        }
        int R = i0 + r;
        unsigned char* base = dst + ((R >> 6) * 16 + g) * 2048;
        *(uint4*)(base + swz((R & 63) * 32))      = make_uint4(w[0], w[1], w[2], w[3]);
        *(uint4*)(base + swz((R & 63) * 32 + 16)) = make_uint4(w[4], w[5], w[6], w[7]);
    }
    if (blk < 8) out[blk * 256 + tid] = b[0];
}

// ---- main: 64x64 tile, 8 warps (4 i-subtiles x 2 j-halves), pipelined LDSM ----
__global__ __launch_bounds__(256) void main_kernel(const float* __restrict__ W,
                                                   float* __restrict__ out) {
    __shared__ __align__(16) unsigned char sA[8 * 2048];   // 16 KB (8 groups/pass)
    __shared__ __align__(16) unsigned char sB[8 * 2048];   // 16 KB
    __shared__ float sW[64];

    const int tid = threadIdx.x;
    const int lane = tid & 31;
    const int wid = tid >> 5;
    const int wi = wid & 3;                 // i-subtile: rows wi*16 .. +15
    const int wj = wid >> 2;                // j-half: cols wj*32 .. +31
    const uint32_t aBase = smem_u32(sA);
    const uint32_t bBase = smem_u32(sB);

    // ldmatrix per-lane offsets (fixed across groups)
    const uint32_t aoff = swz(((wi << 4) + (lane & 15)) * 32 + (lane >> 4) * 16);
    const int jr = (lane & 7) + ((lane >> 4) << 3);
    const uint32_t bkc = (lane >> 3) & 1;
    const uint32_t boff0 = swz((wj * 32 + 0 * 16 + jr) * 32 + bkc * 16);
    const uint32_t boff1 = swz((wj * 32 + 1 * 16 + jr) * 32 + bkc * 16);

    float P[16];
#pragma unroll
    for (int t = 0; t < 16; t++) P[t] = 1.0f;

    if (tid < 64) sW[tid] = W[blockIdx.y * 64 + tid];

    for (int pass = 0; pass < 2; pass++) {
        __syncthreads();
        const uint4* gA = (const uint4*)(g_A + blockIdx.x * 32768 + pass * 16384);
        const uint4* gB = (const uint4*)(g_B + blockIdx.y * 32768 + pass * 16384);
#pragma unroll
        for (int k = 0; k < 4; k++) {
            ((uint4*)sA)[k * 256 + tid] = gA[k * 256 + tid];
            ((uint4*)sB)[k * 256 + tid] = gB[k * 256 + tid];
        }
        __syncthreads();

        // Pipelined over 8 groups: prefetch g+1 fragments during g's MMAs.
        uint32_t a[4], b0[4], b1[4];
        LDSM4(a[0], a[1], a[2], a[3], aBase + aoff);
        LDSM4(b0[0], b0[1], b0[2], b0[3], bBase + boff0);
        LDSM4(b1[0], b1[1], b1[2], b1[3], bBase + boff1);
#pragma unroll
        for (int g = 0; g < 8; g++) {
            uint32_t na[4], nb0[4], nb1[4];
            if (g < 7) {
                LDSM4(na[0], na[1], na[2], na[3], aBase + (g + 1) * 2048 + aoff);
                LDSM4(nb0[0], nb0[1], nb0[2], nb0[3], bBase + (g + 1) * 2048 + boff0);
                LDSM4(nb1[0], nb1[1], nb1[2], nb1[3], bBase + (g + 1) * 2048 + boff1);
            }
            float d[4];
            mma_bf16(d, a[0], a[1], a[2], a[3], b0[0], b0[1]);   // j wj*32 + 0..7
            P[0] *= d[0]; P[1] *= d[1]; P[2] *= d[2]; P[3] *= d[3];
            mma_bf16(d, a[0], a[1], a[2], a[3], b0[2], b0[3]);   // j + 8..15
            P[4] *= d[0]; P[5] *= d[1]; P[6] *= d[2]; P[7] *= d[3];
            mma_bf16(d, a[0], a[1], a[2], a[3], b1[0], b1[1]);   // j + 16..23
            P[8] *= d[0]; P[9] *= d[1]; P[10] *= d[2]; P[11] *= d[3];
            mma_bf16(d, a[0], a[1], a[2], a[3], b1[2], b1[3]);   // j + 24..31
            P[12] *= d[0]; P[13] *= d[1]; P[14] *= d[2]; P[15] *= d[3];
            if (g < 7) {
#pragma unroll
                for (int t = 0; t < 4; t++) { a[t] = na[t]; b0[t] = nb0[t]; b1[t] = nb1[t]; }
            }
        }
    }

    // K = P^2; weight; reduce over the quad (lanes sharing lane>>2).
    // MMA d layout: d0/d1 -> row lane>>2, cols (lane&3)*2 / +1; d2/d3 -> row +8.
    float r0 = 0.0f, r1 = 0.0f;
#pragma unroll
    for (int q = 0; q < 4; q++) {
        int j = wj * 32 + q * 8 + (lane & 3) * 2;
        float w0 = sW[j], w1 = sW[j + 1];
        r0 = fmaf(P[q*4 + 0] * P[q*4 + 0], w0, r0);
        r0 = fmaf(P[q*4 + 1] * P[q*4 + 1], w1, r0);
        r1 = fmaf(P[q*4 + 2] * P[q*4 + 2], w0, r1);
        r1 = fmaf(P[q*4 + 3] * P[q*4 + 3], w1, r1);
    }
    r0 += __shfl_xor_sync(0xffffffffu, r0, 1);
    r0 += __shfl_xor_sync(0xffffffffu, r0, 2);
    r1 += __shfl_xor_sync(0xffffffffu, r1, 1);
    r1 += __shfl_xor_sync(0xffffffffu, r1, 2);
    if ((lane & 3) == 0) {
        int row = blockIdx.x * 64 + wi * 16 + (lane >> 2);
        atomicAdd(&out[row], r0);
        atomicAdd(&out[row + 8], r1);
    }
}

extern "C" void kernel_launch(void* const* d_in, const int* in_sizes, int n_in,
                              void* d_out, int out_size) {
    const float* X  = (const float*)d_in[0];  // [2048, 64]
    const float* Sp = (const float*)d_in[1];  // [1024, 64]
    const float* W  = (const float*)d_in[2];  // [1, 1024]
    const float* b  = (const float*)d_in[3];  // [1]
    float* out = (float*)d_out;               // [2048]

    precomp_kernel<<<192, 256>>>(X, Sp, b, out);   // tables + out=b init

    dim3 grid(BB / 64, SS / 64);                   // 32 x 16 = 512 CTAs, 256 thr
    main_kernel<<<grid, 256>>>(W, out);
}

// round 17
// speedup vs baseline: 1.5363x; 1.0632x over previous
#include <cuda_runtime.h>
#include <cuda_bf16.h>
#include <cstdint>

#define BB 2048
#define SS 1024
#define FF 64
// 16 groups of 4 features. Tables stored directly in mma.m16n8k16 fragment
// order so the main kernel LDG.128s operands straight from gmem (no smem).
//
// A layout: [i-block b (64 rows)][g][s = 16-row subtile 0..3][lane 0..31] x 16B
//   lane record = {a0 @0, a1 @4, a2 @8, a3 @12}
// B layout: [j-block b (64 rows)][g][tp = tile-pair 0..3][lane 0..31] x 16B
//   lane record = {tileEven.b0 @0, .b1 @4, tileOdd.b0 @8, .b1 @12}

__device__ __align__(16) unsigned char g_A[(BB / 64) * 32768];   // 1 MB
__device__ __align__(16) unsigned char g_B[(SS / 64) * 32768];   // 512 KB

__device__ __forceinline__ void mma_bf16(float d[4], uint32_t a0, uint32_t a1, uint32_t a2,
                                         uint32_t a3, uint32_t b0, uint32_t b1) {
    asm("mma.sync.aligned.m16n8k16.row.col.f32.bf16.bf16.f32 "
        "{%0,%1,%2,%3}, {%4,%5,%6,%7}, {%8,%9}, {%10,%11,%12,%13};"
        : "=f"(d[0]), "=f"(d[1]), "=f"(d[2]), "=f"(d[3])
        : "r"(a0), "r"(a1), "r"(a2), "r"(a3), "r"(b0), "r"(b1),
          "f"(0.0f), "f"(0.0f), "f"(0.0f), "f"(0.0f));
}

// ---- precompute: 16-entry group tables, written in fragment order ----
__global__ __launch_bounds__(256) void precomp_kernel(const float* __restrict__ X,
                                                      const float* __restrict__ Sp,
                                                      const float* __restrict__ b,
                                                      float* __restrict__ out) {
    __shared__ float sc[FF][17];
    __shared__ float ss[FF][17];
    const int blk = blockIdx.x;       // [0,128): X rows, [128,192): support rows
    const int tid = threadIdx.x;
    const bool isA = blk < 128;
    const float* src = isA ? X : Sp;
    unsigned char* dst = isA ? g_A : g_B;
    const int i0 = isA ? blk * 16 : (blk - 128) * 16;

    // 16 rows x 64 features, coalesced loads, fast sincos
#pragma unroll
    for (int p = 0; p < 4; p++) {
        int l = p * 256 + tid;
        int r = l >> 6, f = l & 63;
        float s, c;
        __sincosf(0.5f * src[(i0 + r) * FF + f], &s, &c);
        sc[f][r] = c;
        ss[f][r] = s;
    }
    __syncthreads();

    // 16 rows x 16 groups = 256 tasks: 16 sign-pattern products -> 8 packed words
    {
        int r = tid >> 4, g = tid & 15;
        float c0 = sc[4*g+0][r], s0 = ss[4*g+0][r];
        float c1 = sc[4*g+1][r], s1 = ss[4*g+1][r];
        float c2 = sc[4*g+2][r], s2 = ss[4*g+2][r];
        float c3 = sc[4*g+3][r], s3 = ss[4*g+3][r];
        float q01[4] = {c0*c1, s0*c1, c0*s1, s0*s1};   // bit0 -> f0, bit1 -> f1
        float q23[4] = {c2*c3, s2*c3, c2*s3, s2*s3};   // bit0 -> f2, bit1 -> f3
        uint32_t w[8];
#pragma unroll
        for (int mp = 0; mp < 8; mp++) {               // word mp = entries {2mp, 2mp+1}
            float e0 = q01[(2*mp)     & 3] * q23[(2*mp)     >> 2];
            float e1 = q01[(2*mp + 1) & 3] * q23[(2*mp + 1) >> 2];
            w[mp] = (uint32_t)__bfloat16_as_ushort(__float2bfloat16(e0))
                  | ((uint32_t)__bfloat16_as_ushort(__float2bfloat16(e1)) << 16);
        }
        const int R = i0 + r;
        const int blk64 = R >> 6;
        if (isA) {
            // A-frag scatter: row r16 = R&15. r16<8 -> a0 (@0) / a2 (@8) of lanes
            // 4*r16 + m%4 ; r16>=8 -> a1 (@4) / a3 (@12) of lanes 4*(r16-8) + m%4.
            const int s = (R >> 4) & 3, r16 = R & 15;
            unsigned char* base = dst + (((blk64 * 16 + g) * 4 + s) << 9);
            const int lr = (r16 & 7) * 4;
            const int o = (r16 < 8) ? 0 : 4;
#pragma unroll
            for (int m = 0; m < 8; m++) {
                uint32_t off = (lr + (m & 3)) * 16 + o + ((m < 4) ? 0 : 8);
                *(uint32_t*)(base + off) = w[m];
            }
        } else {
            // B-frag scatter: j = R&63; tile = j>>3, tp = tile>>1, ti = tile&1.
            // lane = 4*(j&7) + m%4 ; word -> b0 (m<4) @ ti*8, b1 @ ti*8+4.
            const int jj = R & 63;
            const int tp = jj >> 4, ti = (jj >> 3) & 1;
            unsigned char* base = dst + (((blk64 * 16 + g) * 4 + tp) << 9);
            const int lr = (jj & 7) * 4;
#pragma unroll
            for (int m = 0; m < 8; m++) {
                uint32_t off = (lr + (m & 3)) * 16 + ti * 8 + ((m < 4) ? 0 : 4);
                *(uint32_t*)(base + off) = w[m];
            }
        }
    }
    if (blk < 8) out[blk * 256 + tid] = b[0];
}

// ---- main: smem-free. 64x64 tile, 8 warps (4 i-subtiles x 2 j-halves). ----
__global__ __launch_bounds__(256) void main_kernel(const float* __restrict__ W,
                                                   float* __restrict__ out) {
    const int tid = threadIdx.x;
    const int lane = tid & 31;
    const int wid = tid >> 5;
    const int wi = wid & 3;                 // i-subtile: rows wi*16 .. +15
    const int wj = wid >> 2;                // j-half: cols wj*32 .. +31

    // Fragment streams (uint4 units). Per-group stride = 4*512B = 128 uint4.
    const uint4* pA = (const uint4*)g_A + (uint32_t)((blockIdx.x * 16 * 4 + wi) * 32 + lane);
    const uint4* pB0 = (const uint4*)g_B + (uint32_t)((blockIdx.y * 16 * 4 + wj * 2) * 32 + lane);
    const uint4* pB1 = pB0 + 32;

    float P[16];
#pragma unroll
    for (int t = 0; t < 16; t++) P[t] = 1.0f;

    // Two-deep prefetch pipeline over the 16 groups.
    uint4 fa[2], fb0[2], fb1[2];
    fa[0] = pA[0];    fb0[0] = pB0[0];    fb1[0] = pB1[0];
    fa[1] = pA[128];  fb0[1] = pB0[128];  fb1[1] = pB1[128];

#pragma unroll
    for (int g = 0; g < 16; g++) {
        const int cur = g & 1;
        uint4 a4 = fa[cur], u0 = fb0[cur], u1 = fb1[cur];
        if (g < 14) {
            fa[cur]  = pA[(g + 2) * 128];
            fb0[cur] = pB0[(g + 2) * 128];
            fb1[cur] = pB1[(g + 2) * 128];
        }
        float d[4];
        mma_bf16(d, a4.x, a4.y, a4.z, a4.w, u0.x, u0.y);   // j = wj*32 + 0..7
        P[0] *= d[0]; P[1] *= d[1]; P[2] *= d[2]; P[3] *= d[3];
        mma_bf16(d, a4.x, a4.y, a4.z, a4.w, u0.z, u0.w);   // + 8..15
        P[4] *= d[0]; P[5] *= d[1]; P[6] *= d[2]; P[7] *= d[3];
        mma_bf16(d, a4.x, a4.y, a4.z, a4.w, u1.x, u1.y);   // + 16..23
        P[8] *= d[0]; P[9] *= d[1]; P[10] *= d[2]; P[11] *= d[3];
        mma_bf16(d, a4.x, a4.y, a4.z, a4.w, u1.z, u1.w);   // + 24..31
        P[12] *= d[0]; P[13] *= d[1]; P[14] *= d[2]; P[15] *= d[3];
    }

    // K = P^2; weight (W straight from gmem, L1/L2-resident); quad reduce.
    // d layout: d0/d1 -> row lane>>2, cols (lane&3)*2/+1; d2/d3 -> row +8.
    float r0 = 0.0f, r1 = 0.0f;
#pragma unroll
    for (int q = 0; q < 4; q++) {
        const float2 wv = *(const float2*)&W[blockIdx.y * 64 + wj * 32 + q * 8 + (lane & 3) * 2];
        r0 = fmaf(P[q*4 + 0] * P[q*4 + 0], wv.x, r0);
        r0 = fmaf(P[q*4 + 1] * P[q*4 + 1], wv.y, r0);
        r1 = fmaf(P[q*4 + 2] * P[q*4 + 2], wv.x, r1);
        r1 = fmaf(P[q*4 + 3] * P[q*4 + 3], wv.y, r1);
    }
    r0 += __shfl_xor_sync(0xffffffffu, r0, 1);
    r0 += __shfl_xor_sync(0xffffffffu, r0, 2);
    r1 += __shfl_xor_sync(0xffffffffu, r1, 1);
    r1 += __shfl_xor_sync(0xffffffffu, r1, 2);
    if ((lane & 3) == 0) {
        const int row = blockIdx.x * 64 + wi * 16 + (lane >> 2);
        atomicAdd(&out[row], r0);
        atomicAdd(&out[row + 8], r1);
    }
}

extern "C" void kernel_launch(void* const* d_in, const int* in_sizes, int n_in,
                              void* d_out, int out_size) {
    const float* X  = (const float*)d_in[0];  // [2048, 64]
    const float* Sp = (const float*)d_in[1];  // [1024, 64]
    const float* W  = (const float*)d_in[2];  // [1, 1024]
    const float* b  = (const float*)d_in[3];  // [1]
    float* out = (float*)d_out;               // [2048]

    precomp_kernel<<<192, 256>>>(X, Sp, b, out);   // frag-order tables + out=b

    dim3 grid(BB / 64, SS / 64);                   // 32 x 16 = 512 CTAs, 256 thr
    main_kernel<<<grid, 256>>>(W, out);
}